// round 12
// baseline (speedup 1.0000x reference)
#include <cuda_runtime.h>

#define BB  16
#define LL  128
#define LRR 128
#define VV  32000
#define NONE 0x7fffffff

// Scratch (no allocations allowed anywhere)
__device__ float    g_probs[BB * LL * LRR];   // [b][j][i] — probs[b,0,i,j] in ref notation
__device__ int      g_hard[BB * LL];          // argmax per (b,j)
__device__ float    g_colsum[BB * LL];        // per-(b,j) sum_i p[j][i]
__device__ float    g_partial[BB];            // per-batch weighted prob sum
__device__ unsigned g_fin = 0;                // k2 last-block counter (self-resetting)

// Labels-dtype detect: int64 LE => every odd 32-bit word is a zero high half.
__device__ __forceinline__ void detect_is64(const int* __restrict__ lab_raw,
                                            int t, int* s_is64) {
    if (t < 32) {
        int ok  = (lab_raw[2 * t + 1] == 0);
        int all = __all_sync(0xffffffffu, ok);
        if (t == 0) *s_is64 = all;
    }
}

// ===== k1: __ldcs streaming (measured ~6.9 TB/s) + colsum epilogue =====
// One block per (b,j): streaming reduce of 32000 logits -> (sumexp, argmax),
// gather 128 label probs, and reduce them -> g_colsum[row].
__global__ __launch_bounds__(256) void k1(const float* __restrict__ logits,
                                          const int* __restrict__ lab_raw) {
    const int row  = blockIdx.x;          // b*LL + j
    const int b    = row >> 7;
    const int t    = threadIdx.x;
    const int w    = t >> 5, lane = t & 31;
    const float* __restrict__ base = logits + (size_t)row * VV;

    __shared__ float s_s[8];
    __shared__ float s_v[8];
    __shared__ int   s_i[8];
    __shared__ int   s_lab[LRR];
    __shared__ float s_inv;
    __shared__ int   s_is64;

    detect_is64(lab_raw, t, &s_is64);
    __syncthreads();
    if (t < LRR) {
        s_lab[t] = s_is64 ? lab_raw[(b * LRR + t) * 2] : lab_raw[b * LRR + t];
    }

    float acc0 = 0.0f, acc1 = 0.0f;
    float vmax  = -3.0e38f;
    int   kbest = t;                       // winning quad index (exact elem found later)
    const float4* b4 = (const float4*)base;
    #pragma unroll 4
    for (int k = t; k < VV / 4; k += 256) {
        float4 v = __ldcs(&b4[k]);           // streaming load: evict-first in L2
        acc0 += __expf(v.x) + __expf(v.y);   // MUFU.EX2 path
        acc1 += __expf(v.z) + __expf(v.w);
        float m = fmaxf(fmaxf(v.x, v.y), fmaxf(v.z, v.w));
        bool upd = m > vmax;               // strict > keeps earliest quad (first occurrence)
        kbest = upd ? k : kbest;
        vmax  = upd ? m : vmax;
    }
    float acc = acc0 + acc1;

    // Reconstruct exact element index once
    int imax;
    {
        float4 v = __ldg(&b4[kbest]);
        int i0 = kbest << 2;
        imax = (v.x == vmax) ? i0 : (v.y == vmax) ? i0 + 1
             : (v.z == vmax) ? i0 + 2 : i0 + 3;
    }

    // warp reduce: sum + (max, first-index) — tie -> smaller global index
    #pragma unroll
    for (int off = 16; off; off >>= 1) {
        acc += __shfl_down_sync(0xffffffffu, acc, off);
        float ov = __shfl_down_sync(0xffffffffu, vmax, off);
        int   oi = __shfl_down_sync(0xffffffffu, imax, off);
        if (ov > vmax || (ov == vmax && oi < imax)) { vmax = ov; imax = oi; }
    }
    if (lane == 0) { s_s[w] = acc; s_v[w] = vmax; s_i[w] = imax; }
    __syncthreads();
    if (t == 0) {
        float ts = s_s[0], tv = s_v[0];
        int   ti = s_i[0];
        #pragma unroll
        for (int q = 1; q < 8; q++) {
            ts += s_s[q];
            if (s_v[q] > tv || (s_v[q] == tv && s_i[q] < ti)) { tv = s_v[q]; ti = s_i[q]; }
        }
        s_inv = 1.0f / ts;
        g_hard[row] = ti;
    }
    __syncthreads();

    // Gather label probs + colsum reduce (label loads hit L1/L2 — row just streamed)
    float prob = 0.0f;
    if (t < LRR) {
        prob = __expf(__ldg(&base[s_lab[t]])) * s_inv;
        g_probs[row * LRR + t] = prob;     // probs[b,0,i=t,j], coalesced [b][j][i]
    }
    #pragma unroll
    for (int off = 16; off; off >>= 1)
        prob += __shfl_down_sync(0xffffffffu, prob, off);
    if (lane == 0) s_s[w] = prob;
    __syncthreads();
    if (t == 0) {
        float cs = 0.0f;
        #pragma unroll
        for (int q = 0; q < 8; q++) cs += s_s[q];
        g_colsum[row] = cs;
    }
}

// ===== k2: closed-form from colsums, r4 structure (1024 threads) =====
//   total_b = sum_j 0.1*colsum[j]
//           + sum_{j unmCol} 0.4*(colsum[j] - sum_{i matched} p[j][i])
//           + sum_{i sel} 0.9*p[fj[i]][i]
// Sudoku via 1024-thread scan + shared atomicMin (ints: deterministic).
// Last block (ticket) computes loss = 1 - total/2048; counter self-resets.
__global__ __launch_bounds__(1024) void k2(const int* __restrict__ lab_raw,
                                           float* __restrict__ out) {
    const int b = blockIdx.x;
    const int t = threadIdx.x;

    __shared__ int           s_hard[LL];
    __shared__ float         s_cs[LL];
    __shared__ int           s_lab[LRR];
    __shared__ int           s_fj[LRR];
    __shared__ int           s_colwin[LL];
    __shared__ unsigned char s_sel[LRR];
    __shared__ float         s_red[32];
    __shared__ int           s_is64;

    detect_is64(lab_raw, t, &s_is64);
    if (t < LL) {
        s_hard[t]   = g_hard[b * LL + t];
        s_cs[t]     = g_colsum[b * LL + t];
        s_fj[t]     = NONE;
        s_colwin[t] = NONE;
    }
    __syncthreads();
    if (t < LRR) {
        s_lab[t] = s_is64 ? lab_raw[(b * LRR + t) * 2] : lab_raw[b * LRR + t];
    }
    __syncthreads();

    // Row-first: scan 16384 (i,j) cells, 16 per thread. i fast (stride-1 LDS),
    // s_hard[j] broadcast. atomicMin keeps smallest j per row.
    #pragma unroll
    for (int c = 0; c < LL * LRR; c += 1024) {
        int cell = c + t;
        int i = cell & 127, j = cell >> 7;
        if (s_hard[j] == s_lab[i]) atomicMin(&s_fj[i], j);
    }
    __syncthreads();
    if (t < LRR) {
        int fj = s_fj[t];
        if (fj != NONE) atomicMin(&s_colwin[fj], t);   // column winner = min i
    }
    __syncthreads();
    if (t < LRR) {
        int fj = s_fj[t];
        s_sel[t] = (unsigned char)(fj != NONE && s_colwin[fj] == t);
    }
    __syncthreads();

    // Closed-form contributions: thread t<128 plays row i=t AND column j=t.
    float contrib = 0.0f;
    if (t < LL) {
        const float* __restrict__ pb = g_probs + b * LL * LRR;
        const float cs     = s_cs[t];
        const bool  colUnm = (s_colwin[t] == NONE);
        const int   fj     = s_fj[t];
        contrib = 0.1f * cs;                           // clip-floor term (all cells of col j=t)
        if (colUnm) contrib += 0.4f * cs;              // both-unmatched upgrade for col j=t
        if (s_sel[t]) contrib += 0.9f * pb[fj * LRR + t];  // selected cell of row i=t
        if (colUnm) {
            // matched rows must not count in the both-unmatched term (m ~ 0-2)
            #pragma unroll 8
            for (int i = 0; i < LRR; i++) {
                if (s_sel[i]) contrib -= 0.4f * pb[t * LRR + i];   // p[j=t][i]
            }
        }
    }

    // Block reduce (threads >=128 contribute 0; deterministic order)
    #pragma unroll
    for (int off = 16; off; off >>= 1)
        contrib += __shfl_down_sync(0xffffffffu, contrib, off);
    if ((t & 31) == 0) s_red[t >> 5] = contrib;
    __syncthreads();
    if (t == 0) {
        float s = 0.0f;
        #pragma unroll
        for (int q = 0; q < 32; q++) s += s_red[q];
        g_partial[b] = s;
        __threadfence();                   // release partial before ticket
        unsigned ticket = atomicAdd(&g_fin, 1u);
        if (ticket == BB - 1) {
            __threadfence();               // acquire all partials
            float tot = 0.0f;
            #pragma unroll
            for (int q = 0; q < BB; q++) tot += g_partial[q];
            out[0] = 1.0f - tot * (1.0f / 2048.0f);   // 1 + mean(-2*tot_b/256)
            g_fin = 0;                     // reset for next graph replay
        }
    }
}

extern "C" void kernel_launch(void* const* d_in, const int* in_sizes, int n_in,
                              void* d_out, int out_size) {
    // Resolve input order by element count (logits: 65.5M; labels: 2048/4096 words)
    int li = (in_sizes[0] > in_sizes[1]) ? 0 : 1;
    const float* logits = (const float*)d_in[li];
    const int*   labels = (const int*)d_in[1 - li];

    k1<<<BB * LL, 256>>>(logits, labels);
    k2<<<BB, 1024>>>(labels, (float*)d_out);
}

// round 13
// speedup vs baseline: 1.0491x; 1.0491x over previous
#include <cuda_runtime.h>

#define BB  16
#define LL  128
#define LRR 128
#define VV  32000
#define NONE 0x7fffffff

// Scratch (no allocations allowed anywhere)
__device__ float    g_probs[BB * LL * LRR];   // [b][j][i] — probs[b,0,i,j] in ref notation
__device__ int      g_hard[BB * LL];          // argmax per (b,j)
__device__ float    g_partial[BB];            // per-batch weighted prob sum
__device__ unsigned g_fin = 0;                // k2 last-block counter (self-resetting)

// Labels-dtype detect: int64 LE => every odd 32-bit word is a zero high half.
__device__ __forceinline__ void detect_is64(const int* __restrict__ lab_raw,
                                            int t, int* s_is64) {
    if (t < 32) {
        int ok  = (lab_raw[2 * t + 1] == 0);
        int all = __all_sync(0xffffffffu, ok);
        if (t == 0) *s_is64 = all;
    }
}

// ===== k1: r11 version verbatim (measured ~6.9 TB/s, at the LTS cap) =====
// One block per (b,j): streaming reduce of 32000 logits -> (sumexp, argmax),
// then gather 128 label probs. __ldcs: evict-first for the read-once stream.
__global__ __launch_bounds__(256) void k1(const float* __restrict__ logits,
                                          const int* __restrict__ lab_raw) {
    const int row  = blockIdx.x;          // b*LL + j
    const int b    = row >> 7;
    const int t    = threadIdx.x;
    const int w    = t >> 5, lane = t & 31;
    const float* __restrict__ base = logits + (size_t)row * VV;

    __shared__ float s_s[8];
    __shared__ float s_v[8];
    __shared__ int   s_i[8];
    __shared__ int   s_lab[LRR];
    __shared__ float s_inv;
    __shared__ int   s_is64;

    detect_is64(lab_raw, t, &s_is64);
    __syncthreads();
    if (t < LRR) {
        s_lab[t] = s_is64 ? lab_raw[(b * LRR + t) * 2] : lab_raw[b * LRR + t];
    }

    float acc0 = 0.0f, acc1 = 0.0f;
    float vmax  = -3.0e38f;
    int   kbest = t;                       // winning quad index (exact elem found later)
    const float4* b4 = (const float4*)base;
    #pragma unroll 4
    for (int k = t; k < VV / 4; k += 256) {
        float4 v = __ldcs(&b4[k]);           // streaming load: evict-first in L2
        acc0 += __expf(v.x) + __expf(v.y);   // MUFU.EX2 path
        acc1 += __expf(v.z) + __expf(v.w);
        float m = fmaxf(fmaxf(v.x, v.y), fmaxf(v.z, v.w));
        bool upd = m > vmax;               // strict > keeps earliest quad (first occurrence)
        kbest = upd ? k : kbest;
        vmax  = upd ? m : vmax;
    }
    float acc = acc0 + acc1;

    // Reconstruct exact element index once
    int imax;
    {
        float4 v = __ldg(&b4[kbest]);
        int i0 = kbest << 2;
        imax = (v.x == vmax) ? i0 : (v.y == vmax) ? i0 + 1
             : (v.z == vmax) ? i0 + 2 : i0 + 3;
    }

    // warp reduce: sum + (max, first-index) — tie -> smaller global index
    #pragma unroll
    for (int off = 16; off; off >>= 1) {
        acc += __shfl_down_sync(0xffffffffu, acc, off);
        float ov = __shfl_down_sync(0xffffffffu, vmax, off);
        int   oi = __shfl_down_sync(0xffffffffu, imax, off);
        if (ov > vmax || (ov == vmax && oi < imax)) { vmax = ov; imax = oi; }
    }
    if (lane == 0) { s_s[w] = acc; s_v[w] = vmax; s_i[w] = imax; }
    __syncthreads();
    if (t == 0) {
        float ts = s_s[0], tv = s_v[0];
        int   ti = s_i[0];
        #pragma unroll
        for (int q = 1; q < 8; q++) {
            ts += s_s[q];
            if (s_v[q] > tv || (s_v[q] == tv && s_i[q] < ti)) { tv = s_v[q]; ti = s_i[q]; }
        }
        s_inv = 1.0f / ts;
        g_hard[row] = ti;
    }
    __syncthreads();
    if (t < LRR) {
        // probs[b,0,i=t,j] = exp(logit[label]) / sumexp ; coalesced store [b][j][i]
        g_probs[row * LRR + t] = __expf(__ldg(&base[s_lab[t]])) * s_inv;
    }
}

// ===== k2: r4 structure (measured best 8.4-8.7us) + PDL prologue =====
// Launched with programmatic stream serialization: blocks get on SMs while k1
// is still streaming, preload labels, then park at cudaGridDependencySynchronize
// until k1's completion trigger. Hides launch+ramp behind k1.
__global__ __launch_bounds__(1024) void k2(const int* __restrict__ lab_raw,
                                           float* __restrict__ out) {
    const int b = blockIdx.x;
    const int t = threadIdx.x;

    __shared__ int           s_hard[LL];
    __shared__ int           s_lab[LRR];
    __shared__ int           s_fj[LRR];
    __shared__ int           s_colwin[LL];
    __shared__ unsigned char s_sel[LRR];
    __shared__ float         s_red[32];
    __shared__ int           s_is64;

    // ---- PDL prologue: independent of k1's outputs ----
    detect_is64(lab_raw, t, &s_is64);
    if (t < LL) {
        s_fj[t]     = NONE;
        s_colwin[t] = NONE;
    }
    __syncthreads();
    if (t < LRR) {
        s_lab[t] = s_is64 ? lab_raw[(b * LRR + t) * 2] : lab_raw[b * LRR + t];
    }

    // ---- Wait for k1 grid completion (its g_hard/g_probs now visible) ----
    cudaGridDependencySynchronize();

    if (t < LL) s_hard[t] = g_hard[b * LL + t];
    __syncthreads();

    // Row-first: scan 16384 (i,j) cells, 16 per thread. i fast (stride-1 LDS),
    // s_hard[j] broadcast. atomicMin keeps smallest j per row.
    #pragma unroll
    for (int c = 0; c < LL * LRR; c += 1024) {
        int cell = c + t;
        int i = cell & 127, j = cell >> 7;
        if (s_hard[j] == s_lab[i]) atomicMin(&s_fj[i], j);
    }
    __syncthreads();
    if (t < LRR) {
        int fj = s_fj[t];
        if (fj != NONE) atomicMin(&s_colwin[fj], t);   // column winner = min i
    }
    __syncthreads();
    if (t < LRR) {
        int fj = s_fj[t];
        s_sel[t] = (unsigned char)(fj != NONE && s_colwin[fj] == t);
    }
    __syncthreads();

    // Weighted sum over all cells (16 per thread, coalesced over g_probs [j][i])
    // Weights: 1.0 selected; 0.5 both-row-and-col unmatched; 0.1 otherwise.
    const float* __restrict__ pb = g_probs + b * LL * LRR;
    float acc = 0.0f;
    #pragma unroll
    for (int c = 0; c < LL * LRR; c += 1024) {
        int cell = c + t;
        int i = cell & 127, j = cell >> 7;
        float p = pb[cell];
        float wgt = 0.1f;
        if (s_sel[i] && s_fj[i] == j)              wgt = 1.0f;  // selected match
        else if (!s_sel[i] && s_colwin[j] == NONE) wgt = 0.5f;  // both unmatched
        acc += wgt * p;
    }

    // Block reduce (deterministic order)
    #pragma unroll
    for (int off = 16; off; off >>= 1)
        acc += __shfl_down_sync(0xffffffffu, acc, off);
    if ((t & 31) == 0) s_red[t >> 5] = acc;
    __syncthreads();
    if (t == 0) {
        float s = 0.0f;
        #pragma unroll
        for (int q = 0; q < 32; q++) s += s_red[q];
        g_partial[b] = s;
        __threadfence();                   // release partial before ticket
        unsigned ticket = atomicAdd(&g_fin, 1u);
        if (ticket == BB - 1) {
            __threadfence();               // acquire all partials
            float tot = 0.0f;
            #pragma unroll
            for (int q = 0; q < BB; q++) tot += g_partial[q];
            out[0] = 1.0f - tot * (1.0f / 2048.0f);   // 1 + mean(-2*tot_b/256)
            g_fin = 0;                     // reset for next graph replay
        }
    }
}

extern "C" void kernel_launch(void* const* d_in, const int* in_sizes, int n_in,
                              void* d_out, int out_size) {
    // Resolve input order by element count (logits: 65.5M; labels: 2048/4096 words)
    int li = (in_sizes[0] > in_sizes[1]) ? 0 : 1;
    const float* logits = (const float*)d_in[li];
    const int*   labels = (const int*)d_in[1 - li];

    k1<<<BB * LL, 256>>>(logits, labels);

    // k2 via PDL: may begin (prologue) while k1 runs; gridsync gates the rest.
    cudaLaunchAttribute attrs[1];
    attrs[0].id = cudaLaunchAttributeProgrammaticStreamSerialization;
    attrs[0].val.programmaticStreamSerializationAllowed = 1;
    cudaLaunchConfig_t cfg = {};
    cfg.gridDim  = dim3(BB, 1, 1);
    cfg.blockDim = dim3(1024, 1, 1);
    cfg.dynamicSmemBytes = 0;
    cfg.stream   = 0;
    cfg.attrs    = attrs;
    cfg.numAttrs = 1;
    cudaLaunchKernelEx(&cfg, k2, labels, (float*)d_out);
}